// round 8
// baseline (speedup 1.0000x reference)
#include <cuda_runtime.h>

// ---------------------------------------------------------------------------
// Flow_25108378812712
// ---------------------------------------------------------------------------

#define NC   16
#define DD   128
#define DHWf (128*128*128)
#define DS   64
#define DHWs (64*64*64)

typedef unsigned long long ull;

__device__ float4 g_pos4[DHWf];
__device__ float4 g_fa[DHWs];
__device__ float4 g_fb[DHWs];

// ---------------- packed f32x2 helpers --------------------------------------
__device__ __forceinline__ ull pack2(float lo, float hi) {
    ull r; asm("mov.b64 %0, {%1, %2};" : "=l"(r) : "f"(lo), "f"(hi)); return r;
}
__device__ __forceinline__ void unpack2(ull v, float& lo, float& hi) {
    asm("mov.b64 {%0, %1}, %2;" : "=f"(lo), "=f"(hi) : "l"(v));
}
__device__ __forceinline__ void ffma2(ull& d, ull a, ull b) {
    asm("fma.rn.f32x2 %0, %1, %2, %0;" : "+l"(d) : "l"(a), "l"(b));
}

// ---------------------------------------------------------------------------
// Trilinear samplers, grid_sample(zeros, align_corners) semantics.
// ---------------------------------------------------------------------------
__device__ __forceinline__ float3 sample_flow(const float4* __restrict__ vol,
                                              int D, float pz, float py, float px) {
    float fz = floorf(pz), fy = floorf(py), fx = floorf(px);
    int z0 = (int)fz, y0 = (int)fy, x0 = (int)fx;
    float tz = pz - fz, ty = py - fy, tx = px - fx;

    float wz[2], wy[2], wx[2];
    int zi[2], yi[2], xi[2];
    wz[0] = ((unsigned)z0       < (unsigned)D) ? (1.f - tz) : 0.f;
    wz[1] = ((unsigned)(z0 + 1) < (unsigned)D) ? tz         : 0.f;
    zi[0] = min(max(z0, 0), D - 1);  zi[1] = min(max(z0 + 1, 0), D - 1);
    wy[0] = ((unsigned)y0       < (unsigned)D) ? (1.f - ty) : 0.f;
    wy[1] = ((unsigned)(y0 + 1) < (unsigned)D) ? ty         : 0.f;
    yi[0] = min(max(y0, 0), D - 1);  yi[1] = min(max(y0 + 1, 0), D - 1);
    wx[0] = ((unsigned)x0       < (unsigned)D) ? (1.f - tx) : 0.f;
    wx[1] = ((unsigned)(x0 + 1) < (unsigned)D) ? tx         : 0.f;
    xi[0] = min(max(x0, 0), D - 1);  xi[1] = min(max(x0 + 1, 0), D - 1);

    float az = 0.f, ay = 0.f, ax = 0.f;
#pragma unroll
    for (int a = 0; a < 2; a++)
#pragma unroll
        for (int b = 0; b < 2; b++)
#pragma unroll
            for (int e = 0; e < 2; e++) {
                float w = wz[a] * wy[b] * wx[e];
                float4 v = __ldg(vol + (zi[a] * D + yi[b]) * D + xi[e]);
                az += w * v.x;  ay += w * v.y;  ax += w * v.z;
            }
    return make_float3(az, ay, ax);
}

__device__ __forceinline__ float sample_scalar(const float* __restrict__ vol,
                                               int D, float pz, float py, float px) {
    float fz = floorf(pz), fy = floorf(py), fx = floorf(px);
    int z0 = (int)fz, y0 = (int)fy, x0 = (int)fx;
    float tz = pz - fz, ty = py - fy, tx = px - fx;
    float wz[2], wy[2], wx[2];
    int zi[2], yi[2], xi[2];
    wz[0] = ((unsigned)z0       < (unsigned)D) ? (1.f - tz) : 0.f;
    wz[1] = ((unsigned)(z0 + 1) < (unsigned)D) ? tz         : 0.f;
    zi[0] = min(max(z0, 0), D - 1);  zi[1] = min(max(z0 + 1, 0), D - 1);
    wy[0] = ((unsigned)y0       < (unsigned)D) ? (1.f - ty) : 0.f;
    wy[1] = ((unsigned)(y0 + 1) < (unsigned)D) ? ty         : 0.f;
    yi[0] = min(max(y0, 0), D - 1);  yi[1] = min(max(y0 + 1, 0), D - 1);
    wx[0] = ((unsigned)x0       < (unsigned)D) ? (1.f - tx) : 0.f;
    wx[1] = ((unsigned)(x0 + 1) < (unsigned)D) ? tx         : 0.f;
    xi[0] = min(max(x0, 0), D - 1);  xi[1] = min(max(x0 + 1, 0), D - 1);
    float acc = 0.f;
#pragma unroll
    for (int a = 0; a < 2; a++)
#pragma unroll
        for (int b = 0; b < 2; b++)
#pragma unroll
            for (int e = 0; e < 2; e++)
                acc += (wz[a] * wy[b] * wx[e]) *
                       __ldg(vol + (zi[a] * D + yi[b]) * D + xi[e]);
    return acc;
}

// ---------------------------------------------------------------------------
// Conv3d 16->3, 3x3x3, pad 1.  Tile = (4z, 8y, 128x), 256 threads, 512 blocks.
// Each thread: 8x * 2y * 3oc outputs as 24 packed f32x2 accumulators.
// Weights live in SHARED memory as packed (w,w) pairs: warp-uniform broadcast
// LDS.64 (floor 2, conflict-free) instead of LDC (floor 8, was co-saturating
// with the FMA pipe).  Slab rows read once per kz and shared across (ky,yo).
// ---------------------------------------------------------------------------
#define APPLY(KY, YO)                                                        \
    _Pragma("unroll")                                                        \
    for (int o = 0; o < 3; o++) {                                            \
        ull w0 = wb[o * 432 + kz * 9 + (KY) * 3 + 0];                        \
        ull w1 = wb[o * 432 + kz * 9 + (KY) * 3 + 1];                        \
        ull w2 = wb[o * 432 + kz * 9 + (KY) * 3 + 2];                        \
        _Pragma("unroll")                                                    \
        for (int p = 0; p < 4; p++) {                                        \
            ffma2(acc[o][YO][p], u[p],     w0);                              \
            ffma2(acc[o][YO][p], q[p],     w1);                              \
            ffma2(acc[o][YO][p], u[p + 1], w2);                              \
        }                                                                    \
    }

__global__ void __launch_bounds__(256, 2)
conv3d_kernel(const float* __restrict__ feat,
              const float* __restrict__ wgt,
              const float* __restrict__ bias) {
    __shared__ ull   s_w2[3 * NC * 27];       // packed weights (10.4 KB)
    __shared__ float s_in[60 * 132];          // 6z x 10y x 132 (31.7 KB)

    const int tid = threadIdx.x;              // 0..255
    const int tx  = tid & 15;                 // x oct (8 wide)
    const int zy  = tid >> 4;                 // 0..15
    const int tz  = zy >> 2;                  // 0..3
    const int ty0 = (zy & 3) * 2;             // 0,2,4,6
    const int y0  = blockIdx.x * 8;           // 0..120
    const int z0  = blockIdx.y * 4;           // 0..124

    // pack weights into smem
    for (int i = tid; i < 3 * NC * 27; i += 256) {
        float w = __ldg(wgt + i);
        s_w2[i] = pack2(w, w);
    }

    // zero the two boundary columns once (cols 0 and 129 of 60 rows)
    if (tid < 120) {
        int r = tid % 60, side = tid / 60;
        s_in[r * 132 + side * 129] = 0.f;
    }

    // ---- affine fill mapping: thread -> col c0, rows r0 + 2*yyh + 10*zz ----
    const int r0 = tid >> 7;                  // 0/1
    const int c0 = tid & 127;                 // gx == c0 (interior cols only)
    unsigned vmask = 0;
#pragma unroll
    for (int zz = 0; zz < 6; zz++)
#pragma unroll
        for (int yyh = 0; yyh < 5; yyh++) {
            int gz = z0 - 1 + zz;
            int gy = y0 - 1 + r0 + 2 * yyh;
            if ((unsigned)gz < 128u && (unsigned)gy < 128u)
                vmask |= 1u << (zz * 5 + yyh);
        }
    const int gbase  = (z0 - 1) * 16384 + (y0 - 1 + r0) * 128 + c0;
    const int sstore = r0 * 132 + c0 + 1;

    ull acc[3][2][4];
#pragma unroll
    for (int o = 0; o < 3; o++) {
        float b = __ldg(bias + o);
        ull bb = pack2(b, b);
#pragma unroll
        for (int yo = 0; yo < 2; yo++)
#pragma unroll
            for (int p = 0; p < 4; p++) acc[o][yo][p] = bb;
    }

    // prefetch channel 0
    float pf[30];
#pragma unroll
    for (int zz = 0; zz < 6; zz++)
#pragma unroll
        for (int yyh = 0; yyh < 5; yyh++) {
            int kk = zz * 5 + yyh;
            pf[kk] = (vmask >> kk & 1u)
                   ? __ldg(feat + gbase + zz * 16384 + yyh * 256) : 0.f;
        }

    for (int c = 0; c < NC; c++) {
        __syncthreads();
#pragma unroll
        for (int zz = 0; zz < 6; zz++)
#pragma unroll
            for (int yyh = 0; yyh < 5; yyh++)
                s_in[sstore + zz * 1320 + yyh * 264] = pf[zz * 5 + yyh];
        __syncthreads();

        if (c + 1 < NC) {
            const float* fn = feat + (c + 1) * DHWf;
#pragma unroll
            for (int zz = 0; zz < 6; zz++)
#pragma unroll
                for (int yyh = 0; yyh < 5; yyh++) {
                    int kk = zz * 5 + yyh;
                    pf[kk] = (vmask >> kk & 1u)
                           ? __ldg(fn + gbase + zz * 16384 + yyh * 256) : 0.f;
                }
        }

        const ull* wb = s_w2 + c * 27;        // smem, warp-uniform broadcast
#pragma unroll
        for (int kz = 0; kz < 3; kz++) {
#pragma unroll
            for (int r = 0; r < 4; r++) {     // slab row = (tz+kz)*10 + ty0+r
                const float* rp =
                    &s_in[((tz + kz) * 10 + ty0 + r) * 132 + 8 * tx];
                ulonglong2 A = *reinterpret_cast<const ulonglong2*>(rp);
                ulonglong2 B = *reinterpret_cast<const ulonglong2*>(rp + 4);
                ull u4w = *reinterpret_cast<const ull*>(rp + 8);
                ull u[5] = {A.x, A.y, B.x, B.y, u4w};
                float v1, v2, v3, v4, v5, v6, v7, v8, d0, d1;
                unpack2(A.x, d0, v1);  unpack2(A.y, v2, v3);
                unpack2(B.x, v4, v5);  unpack2(B.y, v6, v7);
                unpack2(u4w, v8, d1);
                ull q[4];
                q[0] = pack2(v1, v2);  q[1] = pack2(v3, v4);
                q[2] = pack2(v5, v6);  q[3] = pack2(v7, v8);

                if (r == 0)      { APPLY(0, 0) }
                else if (r == 1) { APPLY(0, 1)  APPLY(1, 0) }
                else if (r == 2) { APPLY(1, 1)  APPLY(2, 0) }
                else             { APPLY(2, 1) }
            }
        }
    }

    // epilogue: 2y x 8x float4 voxels
#pragma unroll
    for (int yo = 0; yo < 2; yo++) {
        float a[3][8];
#pragma unroll
        for (int o = 0; o < 3; o++)
#pragma unroll
            for (int p = 0; p < 4; p++)
                unpack2(acc[o][yo][p], a[o][2 * p], a[o][2 * p + 1]);
        const int z = z0 + tz, yv = y0 + ty0 + yo;
        const int base = (z * 128 + yv) * 128 + 8 * tx;
#pragma unroll
        for (int xo = 0; xo < 8; xo++)
            g_pos4[base + xo] = make_float4(a[0][xo], a[1][xo], a[2][xo], 0.f);
    }
}

// ---------------------------------------------------------------------------
// f0 = resize(pos_flow, 64^3) * (1/2) * (1/2^7)
// ---------------------------------------------------------------------------
__global__ void resize_down_kernel() {
    int idx = blockIdx.x * blockDim.x + threadIdx.x;
    if (idx >= DHWs) return;
    int k = idx & 63, j = (idx >> 6) & 63, i = idx >> 12;
    const float S = 127.f / 63.f;
    float3 o = sample_flow(g_pos4, DD, i * S, j * S, k * S);
    const float sc = 1.f / 256.f;
    g_fa[idx] = make_float4(o.x * sc, o.y * sc, o.z * sc, 0.f);
}

// ---------------------------------------------------------------------------
// scaling-and-squaring step: dst = f + warp(f, f)
// ---------------------------------------------------------------------------
__global__ void vecint_kernel(int it) {
    const float4* __restrict__ src = (it & 1) ? g_fb : g_fa;
    float4*       __restrict__ dst = (it & 1) ? g_fa : g_fb;
    int idx = blockIdx.x * blockDim.x + threadIdx.x;
    if (idx >= DHWs) return;
    int k = idx & 63, j = (idx >> 6) & 63, i = idx >> 12;
    float4 f = __ldg(src + idx);
    float3 o = sample_flow(src, DS, i + f.x, j + f.y, k + f.z);
    dst[idx] = make_float4(f.x + o.x, f.y + o.y, f.z + o.z, 0.f);
}

// ---------------------------------------------------------------------------
// flow = resize(f * 2, 128^3); moved = warp(label, flow)
// ---------------------------------------------------------------------------
__global__ void upsample_warp_kernel(const float* __restrict__ label,
                                     float* __restrict__ out) {
    int t = blockIdx.x * blockDim.x + threadIdx.x;
    if (t >= DHWf / 4) return;
    int x0 = (t & 31) * 4;
    int y  = (t >> 5) & 127;
    int z  = t >> 12;
    const float S = 63.f / 127.f;

    float pz = z * S, py = y * S;
    float fz = floorf(pz), fy = floorf(py);
    int z0 = (int)fz, y0 = (int)fy;
    float tz = pz - fz, ty = py - fy;
    int z1 = min(z0 + 1, DS - 1), y1 = min(y0 + 1, DS - 1);
    float wzy[4];
    wzy[0] = (1.f - tz) * (1.f - ty);
    wzy[1] = (1.f - tz) * ty;
    wzy[2] = tz * (1.f - ty);
    wzy[3] = tz * ty;
    const float4* rowp[4];
    rowp[0] = g_fb + (z0 * DS + y0) * DS;
    rowp[1] = g_fb + (z0 * DS + y1) * DS;
    rowp[2] = g_fb + (z1 * DS + y0) * DS;
    rowp[3] = g_fb + (z1 * DS + y1) * DS;

    float4 mv, oz, oy, ox;
    float* pm = &mv.x; float* pzo = &oz.x; float* pyo = &oy.x; float* pxo = &ox.x;
#pragma unroll
    for (int q = 0; q < 4; q++) {
        int x = x0 + q;
        float px = x * S;
        float fx = floorf(px);
        int xi0 = (int)fx;
        float txf = px - fx;
        int xi1 = min(xi0 + 1, DS - 1);

        float az = 0.f, ay = 0.f, ax = 0.f;
#pragma unroll
        for (int ab = 0; ab < 4; ab++) {
            float4 v0 = __ldg(rowp[ab] + xi0);
            float4 v1 = __ldg(rowp[ab] + xi1);
            float w0 = wzy[ab] * (1.f - txf);
            float w1 = wzy[ab] * txf;
            az += w0 * v0.x + w1 * v1.x;
            ay += w0 * v0.y + w1 * v1.y;
            ax += w0 * v0.z + w1 * v1.z;
        }
        float flz = 2.f * az, fly = 2.f * ay, flx = 2.f * ax;
        pzo[q] = flz;  pyo[q] = fly;  pxo[q] = flx;
        pm[q] = sample_scalar(label, DD, z + flz, y + fly, x + flx);
    }
    int base = (z * 128 + y) * 128 + x0;
    *reinterpret_cast<float4*>(out + base)            = mv;
    *reinterpret_cast<float4*>(out + DHWf + base)     = oz;
    *reinterpret_cast<float4*>(out + 2 * DHWf + base) = oy;
    *reinterpret_cast<float4*>(out + 3 * DHWf + base) = ox;
}

// ---------------------------------------------------------------------------
extern "C" void kernel_launch(void* const* d_in, const int* in_sizes, int n_in,
                              void* d_out, int out_size) {
    const float* feat  = (const float*)d_in[0];
    const float* label = (const float*)d_in[1];
    const float* wgt   = (const float*)d_in[2];
    const float* bias  = (const float*)d_in[3];
    float* out = (float*)d_out;

    conv3d_kernel<<<dim3(16, 32), 256>>>(feat, wgt, bias);
    resize_down_kernel<<<DHWs / 256, 256>>>();
    for (int it = 0; it < 7; it++)
        vecint_kernel<<<DHWs / 256, 256>>>(it);
    upsample_warp_kernel<<<(DHWf / 4) / 256, 256>>>(label, out);
}

// round 9
// speedup vs baseline: 1.0013x; 1.0013x over previous
#include <cuda_runtime.h>

// ---------------------------------------------------------------------------
// Flow_25108378812712
// ---------------------------------------------------------------------------

#define NC   16
#define DD   128
#define DHWf (128*128*128)
#define DS   64
#define DHWs (64*64*64)

typedef unsigned long long ull;

__device__ float4 g_pos4[DHWf];
__device__ float4 g_fa[DHWs];
__device__ float4 g_fb[DHWs];

// ---------------- packed f32x2 helpers --------------------------------------
__device__ __forceinline__ ull pack2(float lo, float hi) {
    ull r; asm("mov.b64 %0, {%1, %2};" : "=l"(r) : "f"(lo), "f"(hi)); return r;
}
__device__ __forceinline__ void unpack2(ull v, float& lo, float& hi) {
    asm("mov.b64 {%0, %1}, %2;" : "=f"(lo), "=f"(hi) : "l"(v));
}
__device__ __forceinline__ void ffma2(ull& d, ull a, ull b) {
    asm("fma.rn.f32x2 %0, %1, %2, %0;" : "+l"(d) : "l"(a), "l"(b));
}

// ---------------------------------------------------------------------------
// Trilinear samplers, grid_sample(zeros, align_corners) semantics.
// ---------------------------------------------------------------------------
__device__ __forceinline__ float3 sample_flow(const float4* __restrict__ vol,
                                              int D, float pz, float py, float px) {
    float fz = floorf(pz), fy = floorf(py), fx = floorf(px);
    int z0 = (int)fz, y0 = (int)fy, x0 = (int)fx;
    float tz = pz - fz, ty = py - fy, tx = px - fx;

    float wz[2], wy[2], wx[2];
    int zi[2], yi[2], xi[2];
    wz[0] = ((unsigned)z0       < (unsigned)D) ? (1.f - tz) : 0.f;
    wz[1] = ((unsigned)(z0 + 1) < (unsigned)D) ? tz         : 0.f;
    zi[0] = min(max(z0, 0), D - 1);  zi[1] = min(max(z0 + 1, 0), D - 1);
    wy[0] = ((unsigned)y0       < (unsigned)D) ? (1.f - ty) : 0.f;
    wy[1] = ((unsigned)(y0 + 1) < (unsigned)D) ? ty         : 0.f;
    yi[0] = min(max(y0, 0), D - 1);  yi[1] = min(max(y0 + 1, 0), D - 1);
    wx[0] = ((unsigned)x0       < (unsigned)D) ? (1.f - tx) : 0.f;
    wx[1] = ((unsigned)(x0 + 1) < (unsigned)D) ? tx         : 0.f;
    xi[0] = min(max(x0, 0), D - 1);  xi[1] = min(max(x0 + 1, 0), D - 1);

    float az = 0.f, ay = 0.f, ax = 0.f;
#pragma unroll
    for (int a = 0; a < 2; a++)
#pragma unroll
        for (int b = 0; b < 2; b++)
#pragma unroll
            for (int e = 0; e < 2; e++) {
                float w = wz[a] * wy[b] * wx[e];
                float4 v = __ldg(vol + (zi[a] * D + yi[b]) * D + xi[e]);
                az += w * v.x;  ay += w * v.y;  ax += w * v.z;
            }
    return make_float3(az, ay, ax);
}

__device__ __forceinline__ float sample_scalar(const float* __restrict__ vol,
                                               int D, float pz, float py, float px) {
    float fz = floorf(pz), fy = floorf(py), fx = floorf(px);
    int z0 = (int)fz, y0 = (int)fy, x0 = (int)fx;
    float tz = pz - fz, ty = py - fy, tx = px - fx;
    float wz[2], wy[2], wx[2];
    int zi[2], yi[2], xi[2];
    wz[0] = ((unsigned)z0       < (unsigned)D) ? (1.f - tz) : 0.f;
    wz[1] = ((unsigned)(z0 + 1) < (unsigned)D) ? tz         : 0.f;
    zi[0] = min(max(z0, 0), D - 1);  zi[1] = min(max(z0 + 1, 0), D - 1);
    wy[0] = ((unsigned)y0       < (unsigned)D) ? (1.f - ty) : 0.f;
    wy[1] = ((unsigned)(y0 + 1) < (unsigned)D) ? ty         : 0.f;
    yi[0] = min(max(y0, 0), D - 1);  yi[1] = min(max(y0 + 1, 0), D - 1);
    wx[0] = ((unsigned)x0       < (unsigned)D) ? (1.f - tx) : 0.f;
    wx[1] = ((unsigned)(x0 + 1) < (unsigned)D) ? tx         : 0.f;
    xi[0] = min(max(x0, 0), D - 1);  xi[1] = min(max(x0 + 1, 0), D - 1);
    float acc = 0.f;
#pragma unroll
    for (int a = 0; a < 2; a++)
#pragma unroll
        for (int b = 0; b < 2; b++)
#pragma unroll
            for (int e = 0; e < 2; e++)
                acc += (wz[a] * wy[b] * wx[e]) *
                       __ldg(vol + (zi[a] * D + yi[b]) * D + xi[e]);
    return acc;
}

// ---------------------------------------------------------------------------
// Conv3d 16->3, 3x3x3, pad 1.  Tile = (4z, 8y, 128x), 256 threads, 512 blocks.
// Each thread: 8x * 2y * 3oc outputs as 24 packed f32x2 accumulators.
// Weights live in SHARED memory as packed (w,w) pairs: warp-uniform broadcast
// LDS.64 (floor 2, conflict-free) instead of LDC (floor 8, was co-saturating
// with the FMA pipe).  Slab rows read once per kz and shared across (ky,yo).
// ---------------------------------------------------------------------------
#define APPLY(KY, YO)                                                        \
    _Pragma("unroll")                                                        \
    for (int o = 0; o < 3; o++) {                                            \
        ull w0 = wb[o * 432 + kz * 9 + (KY) * 3 + 0];                        \
        ull w1 = wb[o * 432 + kz * 9 + (KY) * 3 + 1];                        \
        ull w2 = wb[o * 432 + kz * 9 + (KY) * 3 + 2];                        \
        _Pragma("unroll")                                                    \
        for (int p = 0; p < 4; p++) {                                        \
            ffma2(acc[o][YO][p], u[p],     w0);                              \
            ffma2(acc[o][YO][p], q[p],     w1);                              \
            ffma2(acc[o][YO][p], u[p + 1], w2);                              \
        }                                                                    \
    }

__global__ void __launch_bounds__(256, 2)
conv3d_kernel(const float* __restrict__ feat,
              const float* __restrict__ wgt,
              const float* __restrict__ bias) {
    __shared__ ull   s_w2[3 * NC * 27];       // packed weights (10.4 KB)
    __shared__ float s_in[60 * 132];          // 6z x 10y x 132 (31.7 KB)

    const int tid = threadIdx.x;              // 0..255
    const int tx  = tid & 15;                 // x oct (8 wide)
    const int zy  = tid >> 4;                 // 0..15
    const int tz  = zy >> 2;                  // 0..3
    const int ty0 = (zy & 3) * 2;             // 0,2,4,6
    const int y0  = blockIdx.x * 8;           // 0..120
    const int z0  = blockIdx.y * 4;           // 0..124

    // pack weights into smem
    for (int i = tid; i < 3 * NC * 27; i += 256) {
        float w = __ldg(wgt + i);
        s_w2[i] = pack2(w, w);
    }

    // zero the two boundary columns once (cols 0 and 129 of 60 rows)
    if (tid < 120) {
        int r = tid % 60, side = tid / 60;
        s_in[r * 132 + side * 129] = 0.f;
    }

    // ---- affine fill mapping: thread -> col c0, rows r0 + 2*yyh + 10*zz ----
    const int r0 = tid >> 7;                  // 0/1
    const int c0 = tid & 127;                 // gx == c0 (interior cols only)
    unsigned vmask = 0;
#pragma unroll
    for (int zz = 0; zz < 6; zz++)
#pragma unroll
        for (int yyh = 0; yyh < 5; yyh++) {
            int gz = z0 - 1 + zz;
            int gy = y0 - 1 + r0 + 2 * yyh;
            if ((unsigned)gz < 128u && (unsigned)gy < 128u)
                vmask |= 1u << (zz * 5 + yyh);
        }
    const int gbase  = (z0 - 1) * 16384 + (y0 - 1 + r0) * 128 + c0;
    const int sstore = r0 * 132 + c0 + 1;

    ull acc[3][2][4];
#pragma unroll
    for (int o = 0; o < 3; o++) {
        float b = __ldg(bias + o);
        ull bb = pack2(b, b);
#pragma unroll
        for (int yo = 0; yo < 2; yo++)
#pragma unroll
            for (int p = 0; p < 4; p++) acc[o][yo][p] = bb;
    }

    // prefetch channel 0
    float pf[30];
#pragma unroll
    for (int zz = 0; zz < 6; zz++)
#pragma unroll
        for (int yyh = 0; yyh < 5; yyh++) {
            int kk = zz * 5 + yyh;
            pf[kk] = (vmask >> kk & 1u)
                   ? __ldg(feat + gbase + zz * 16384 + yyh * 256) : 0.f;
        }

    for (int c = 0; c < NC; c++) {
        __syncthreads();
#pragma unroll
        for (int zz = 0; zz < 6; zz++)
#pragma unroll
            for (int yyh = 0; yyh < 5; yyh++)
                s_in[sstore + zz * 1320 + yyh * 264] = pf[zz * 5 + yyh];
        __syncthreads();

        if (c + 1 < NC) {
            const float* fn = feat + (c + 1) * DHWf;
#pragma unroll
            for (int zz = 0; zz < 6; zz++)
#pragma unroll
                for (int yyh = 0; yyh < 5; yyh++) {
                    int kk = zz * 5 + yyh;
                    pf[kk] = (vmask >> kk & 1u)
                           ? __ldg(fn + gbase + zz * 16384 + yyh * 256) : 0.f;
                }
        }

        const ull* wb = s_w2 + c * 27;        // smem, warp-uniform broadcast
#pragma unroll
        for (int kz = 0; kz < 3; kz++) {
#pragma unroll
            for (int r = 0; r < 4; r++) {     // slab row = (tz+kz)*10 + ty0+r
                const float* rp =
                    &s_in[((tz + kz) * 10 + ty0 + r) * 132 + 8 * tx];
                ulonglong2 A = *reinterpret_cast<const ulonglong2*>(rp);
                ulonglong2 B = *reinterpret_cast<const ulonglong2*>(rp + 4);
                ull u4w = *reinterpret_cast<const ull*>(rp + 8);
                ull u[5] = {A.x, A.y, B.x, B.y, u4w};
                float v1, v2, v3, v4, v5, v6, v7, v8, d0, d1;
                unpack2(A.x, d0, v1);  unpack2(A.y, v2, v3);
                unpack2(B.x, v4, v5);  unpack2(B.y, v6, v7);
                unpack2(u4w, v8, d1);
                ull q[4];
                q[0] = pack2(v1, v2);  q[1] = pack2(v3, v4);
                q[2] = pack2(v5, v6);  q[3] = pack2(v7, v8);

                if (r == 0)      { APPLY(0, 0) }
                else if (r == 1) { APPLY(0, 1)  APPLY(1, 0) }
                else if (r == 2) { APPLY(1, 1)  APPLY(2, 0) }
                else             { APPLY(2, 1) }
            }
        }
    }

    // epilogue: 2y x 8x float4 voxels
#pragma unroll
    for (int yo = 0; yo < 2; yo++) {
        float a[3][8];
#pragma unroll
        for (int o = 0; o < 3; o++)
#pragma unroll
            for (int p = 0; p < 4; p++)
                unpack2(acc[o][yo][p], a[o][2 * p], a[o][2 * p + 1]);
        const int z = z0 + tz, yv = y0 + ty0 + yo;
        const int base = (z * 128 + yv) * 128 + 8 * tx;
#pragma unroll
        for (int xo = 0; xo < 8; xo++)
            g_pos4[base + xo] = make_float4(a[0][xo], a[1][xo], a[2][xo], 0.f);
    }
}

// ---------------------------------------------------------------------------
// f0 = resize(pos_flow, 64^3) * (1/2) * (1/2^7)
// ---------------------------------------------------------------------------
__global__ void resize_down_kernel() {
    int idx = blockIdx.x * blockDim.x + threadIdx.x;
    if (idx >= DHWs) return;
    int k = idx & 63, j = (idx >> 6) & 63, i = idx >> 12;
    const float S = 127.f / 63.f;
    float3 o = sample_flow(g_pos4, DD, i * S, j * S, k * S);
    const float sc = 1.f / 256.f;
    g_fa[idx] = make_float4(o.x * sc, o.y * sc, o.z * sc, 0.f);
}

// ---------------------------------------------------------------------------
// scaling-and-squaring step: dst = f + warp(f, f)
// ---------------------------------------------------------------------------
__global__ void vecint_kernel(int it) {
    const float4* __restrict__ src = (it & 1) ? g_fb : g_fa;
    float4*       __restrict__ dst = (it & 1) ? g_fa : g_fb;
    int idx = blockIdx.x * blockDim.x + threadIdx.x;
    if (idx >= DHWs) return;
    int k = idx & 63, j = (idx >> 6) & 63, i = idx >> 12;
    float4 f = __ldg(src + idx);
    float3 o = sample_flow(src, DS, i + f.x, j + f.y, k + f.z);
    dst[idx] = make_float4(f.x + o.x, f.y + o.y, f.z + o.z, 0.f);
}

// ---------------------------------------------------------------------------
// flow = resize(f * 2, 128^3); moved = warp(label, flow)
// ---------------------------------------------------------------------------
__global__ void upsample_warp_kernel(const float* __restrict__ label,
                                     float* __restrict__ out) {
    int t = blockIdx.x * blockDim.x + threadIdx.x;
    if (t >= DHWf / 4) return;
    int x0 = (t & 31) * 4;
    int y  = (t >> 5) & 127;
    int z  = t >> 12;
    const float S = 63.f / 127.f;

    float pz = z * S, py = y * S;
    float fz = floorf(pz), fy = floorf(py);
    int z0 = (int)fz, y0 = (int)fy;
    float tz = pz - fz, ty = py - fy;
    int z1 = min(z0 + 1, DS - 1), y1 = min(y0 + 1, DS - 1);
    float wzy[4];
    wzy[0] = (1.f - tz) * (1.f - ty);
    wzy[1] = (1.f - tz) * ty;
    wzy[2] = tz * (1.f - ty);
    wzy[3] = tz * ty;
    const float4* rowp[4];
    rowp[0] = g_fb + (z0 * DS + y0) * DS;
    rowp[1] = g_fb + (z0 * DS + y1) * DS;
    rowp[2] = g_fb + (z1 * DS + y0) * DS;
    rowp[3] = g_fb + (z1 * DS + y1) * DS;

    float4 mv, oz, oy, ox;
    float* pm = &mv.x; float* pzo = &oz.x; float* pyo = &oy.x; float* pxo = &ox.x;
#pragma unroll
    for (int q = 0; q < 4; q++) {
        int x = x0 + q;
        float px = x * S;
        float fx = floorf(px);
        int xi0 = (int)fx;
        float txf = px - fx;
        int xi1 = min(xi0 + 1, DS - 1);

        float az = 0.f, ay = 0.f, ax = 0.f;
#pragma unroll
        for (int ab = 0; ab < 4; ab++) {
            float4 v0 = __ldg(rowp[ab] + xi0);
            float4 v1 = __ldg(rowp[ab] + xi1);
            float w0 = wzy[ab] * (1.f - txf);
            float w1 = wzy[ab] * txf;
            az += w0 * v0.x + w1 * v1.x;
            ay += w0 * v0.y + w1 * v1.y;
            ax += w0 * v0.z + w1 * v1.z;
        }
        float flz = 2.f * az, fly = 2.f * ay, flx = 2.f * ax;
        pzo[q] = flz;  pyo[q] = fly;  pxo[q] = flx;
        pm[q] = sample_scalar(label, DD, z + flz, y + fly, x + flx);
    }
    int base = (z * 128 + y) * 128 + x0;
    *reinterpret_cast<float4*>(out + base)            = mv;
    *reinterpret_cast<float4*>(out + DHWf + base)     = oz;
    *reinterpret_cast<float4*>(out + 2 * DHWf + base) = oy;
    *reinterpret_cast<float4*>(out + 3 * DHWf + base) = ox;
}

// ---------------------------------------------------------------------------
extern "C" void kernel_launch(void* const* d_in, const int* in_sizes, int n_in,
                              void* d_out, int out_size) {
    const float* feat  = (const float*)d_in[0];
    const float* label = (const float*)d_in[1];
    const float* wgt   = (const float*)d_in[2];
    const float* bias  = (const float*)d_in[3];
    float* out = (float*)d_out;

    conv3d_kernel<<<dim3(16, 32), 256>>>(feat, wgt, bias);
    resize_down_kernel<<<DHWs / 256, 256>>>();
    for (int it = 0; it < 7; it++)
        vecint_kernel<<<DHWs / 256, 256>>>(it);
    upsample_warp_kernel<<<(DHWf / 4) / 256, 256>>>(label, out);
}

// round 12
// speedup vs baseline: 1.0323x; 1.0309x over previous
#include <cuda_runtime.h>
#include <cuda_bf16.h>
#include <cstdint>

// ---------------------------------------------------------------------------
// Flow_25108378812712 — conv3d via 3-term-split bf16 mma.sync + flow pipeline
// ---------------------------------------------------------------------------

#define NC   16
#define DD   128
#define DHWf (128*128*128)
#define DS   64
#define DHWs (64*64*64)

typedef unsigned long long ull;

__device__ float4 g_pos4[DHWf];
__device__ float4 g_fa[DHWs];
__device__ float4 g_fb[DHWs];

__device__ __forceinline__ uint32_t smem_to_u32(const void* p) {
    uint32_t a;
    asm("{ .reg .u64 t; cvta.to.shared.u64 t, %1; cvt.u32.u64 %0, t; }"
        : "=r"(a) : "l"(p));
    return a;
}
__device__ __forceinline__ uint32_t packbf(__nv_bfloat16 a, __nv_bfloat16 b) {
    __nv_bfloat162 t = __halves2bfloat162(a, b);   // .x = a (low half)
    return *reinterpret_cast<uint32_t*>(&t);
}

// ---------------------------------------------------------------------------
// Trilinear samplers, grid_sample(zeros, align_corners) semantics.
// ---------------------------------------------------------------------------
__device__ __forceinline__ float3 sample_flow(const float4* __restrict__ vol,
                                              int D, float pz, float py, float px) {
    float fz = floorf(pz), fy = floorf(py), fx = floorf(px);
    int z0 = (int)fz, y0 = (int)fy, x0 = (int)fx;
    float tz = pz - fz, ty = py - fy, tx = px - fx;

    float wz[2], wy[2], wx[2];
    int zi[2], yi[2], xi[2];
    wz[0] = ((unsigned)z0       < (unsigned)D) ? (1.f - tz) : 0.f;
    wz[1] = ((unsigned)(z0 + 1) < (unsigned)D) ? tz         : 0.f;
    zi[0] = min(max(z0, 0), D - 1);  zi[1] = min(max(z0 + 1, 0), D - 1);
    wy[0] = ((unsigned)y0       < (unsigned)D) ? (1.f - ty) : 0.f;
    wy[1] = ((unsigned)(y0 + 1) < (unsigned)D) ? ty         : 0.f;
    yi[0] = min(max(y0, 0), D - 1);  yi[1] = min(max(y0 + 1, 0), D - 1);
    wx[0] = ((unsigned)x0       < (unsigned)D) ? (1.f - tx) : 0.f;
    wx[1] = ((unsigned)(x0 + 1) < (unsigned)D) ? tx         : 0.f;
    xi[0] = min(max(x0, 0), D - 1);  xi[1] = min(max(x0 + 1, 0), D - 1);

    float az = 0.f, ay = 0.f, ax = 0.f;
#pragma unroll
    for (int a = 0; a < 2; a++)
#pragma unroll
        for (int b = 0; b < 2; b++)
#pragma unroll
            for (int e = 0; e < 2; e++) {
                float w = wz[a] * wy[b] * wx[e];
                float4 v = __ldg(vol + (zi[a] * D + yi[b]) * D + xi[e]);
                az += w * v.x;  ay += w * v.y;  ax += w * v.z;
            }
    return make_float3(az, ay, ax);
}

__device__ __forceinline__ float sample_scalar(const float* __restrict__ vol,
                                               int D, float pz, float py, float px) {
    float fz = floorf(pz), fy = floorf(py), fx = floorf(px);
    int z0 = (int)fz, y0 = (int)fy, x0 = (int)fx;
    float tz = pz - fz, ty = py - fy, tx = px - fx;
    float wz[2], wy[2], wx[2];
    int zi[2], yi[2], xi[2];
    wz[0] = ((unsigned)z0       < (unsigned)D) ? (1.f - tz) : 0.f;
    wz[1] = ((unsigned)(z0 + 1) < (unsigned)D) ? tz         : 0.f;
    zi[0] = min(max(z0, 0), D - 1);  zi[1] = min(max(z0 + 1, 0), D - 1);
    wy[0] = ((unsigned)y0       < (unsigned)D) ? (1.f - ty) : 0.f;
    wy[1] = ((unsigned)(y0 + 1) < (unsigned)D) ? ty         : 0.f;
    yi[0] = min(max(y0, 0), D - 1);  yi[1] = min(max(y0 + 1, 0), D - 1);
    wx[0] = ((unsigned)x0       < (unsigned)D) ? (1.f - tx) : 0.f;
    wx[1] = ((unsigned)(x0 + 1) < (unsigned)D) ? tx         : 0.f;
    xi[0] = min(max(x0, 0), D - 1);  xi[1] = min(max(x0 + 1, 0), D - 1);
    float acc = 0.f;
#pragma unroll
    for (int a = 0; a < 2; a++)
#pragma unroll
        for (int b = 0; b < 2; b++)
#pragma unroll
            for (int e = 0; e < 2; e++)
                acc += (wz[a] * wy[b] * wx[e]) *
                       __ldg(vol + (zi[a] * D + yi[b]) * D + xi[e]);
    return acc;
}

// ---------------------------------------------------------------------------
// Conv3d 16->3, 3x3x3, pad 1 on tensor cores with 3-term bf16 split:
//   a*w ~= ah*wh + ah*wl + al*wh   (al = bf16(a - ah), wl = bf16(w - wh))
// Tile (4z, 4y, 128x), 512 threads (16 warps), warp = (oz 0..3, oy 0..3).
// Feature-z streamed: one (6y x 132x) hi+lo plane pair in smem at a time;
// for fz = 0..5 each warp fires kz = fz - oz (if in [0,2]) taps.
// Row = 32 B (16 ch bf16); swizzle (cx*32 + h*16) ^ ((cx&4)<<2) keeps
// ldmatrix / STS conflict-free.  Fragment layouts identical to the
// silicon-verified R10 kernel.
// ---------------------------------------------------------------------------
#define PLANE  25344                 // 6 rows * 132 cols * 32 B
#define BHOFF  50688
#define BLOFF  57600
#define CSMEM  64512                 // staging (32 KB) reuses [0, 32768)

__global__ void __launch_bounds__(512, 2)
conv3d_tc_kernel(const float* __restrict__ feat,
                 const float* __restrict__ wgt,
                 const float* __restrict__ bias) {
    extern __shared__ char dsm[];
    const int tid  = threadIdx.x;
    const int lane = tid & 31;
    const int wid  = tid >> 5;        // 0..15
    const int oz_w = wid >> 2;        // output z within tile
    const int oy_w = wid & 3;         // output y within tile
    const int y0   = blockIdx.x * 4;
    const int z0   = blockIdx.y * 4;
    const uint32_t sb = smem_to_u32(dsm);

    // ---- B fragments (hi and lo), layout as R10 (verified) -----------------
    for (int i = tid; i < 27 * 32; i += 512) {
        int t  = i >> 5;
        int ln = i & 31;
        int n  = ln >> 2;
        int c0 = (ln & 3) * 2;
        uint32_t h0 = 0, h1 = 0, l0 = 0, l1 = 0;
        if (n < 3) {
            const float* wp = wgt + n * 432 + t;    // w[n][c][t], t = kz*9+ky*3+kx
            float wa = __ldg(wp + c0 * 27),       wb = __ldg(wp + (c0 + 1) * 27);
            float wc = __ldg(wp + (c0 + 8) * 27), wd = __ldg(wp + (c0 + 9) * 27);
            __nv_bfloat16 ha = __float2bfloat16(wa), hb = __float2bfloat16(wb);
            __nv_bfloat16 hc = __float2bfloat16(wc), hd = __float2bfloat16(wd);
            h0 = packbf(ha, hb);  h1 = packbf(hc, hd);
            l0 = packbf(__float2bfloat16(wa - __bfloat162float(ha)),
                        __float2bfloat16(wb - __bfloat162float(hb)));
            l1 = packbf(__float2bfloat16(wc - __bfloat162float(hc)),
                        __float2bfloat16(wd - __bfloat162float(hd)));
        }
        *reinterpret_cast<uint2*>(dsm + BHOFF + t * 256 + ln * 8) = make_uint2(h0, h1);
        *reinterpret_cast<uint2*>(dsm + BLOFF + t * 256 + ln * 8) = make_uint2(l0, l1);
    }

    // ---- per-lane ldmatrix offsets (row r, half h; col = g*16 + r + kx) ----
    const int rA = (lane & 7) + ((lane >> 3) & 1) * 8;
    const int hA = lane >> 4;
    uint32_t off[3];
#pragma unroll
    for (int kx = 0; kx < 3; kx++) {
        int s = rA + kx;
        off[kx] = (uint32_t)((s * 32 + hA * 16) ^ ((s & 4) << 2));
    }

    const int n0 = (lane & 3) * 2;
    float b0i = (n0 == 0) ? __ldg(bias + 0) : (n0 == 2 ? __ldg(bias + 2) : 0.f);
    float b1i = (n0 == 0) ? __ldg(bias + 1) : 0.f;
    float acc[8][4];
#pragma unroll
    for (int g = 0; g < 8; g++) {
        acc[g][0] = b0i; acc[g][1] = b1i; acc[g][2] = b0i; acc[g][3] = b1i;
    }

#pragma unroll 1
    for (int fz = 0; fz < 6; fz++) {
        __syncthreads();              // prior MMAs (and B-frag init) complete
        // ---- fill plane fz: rows sy 0..5, cols cx 0..131 (gx = cx-1) -------
        int gz = z0 - 1 + fz;
        for (int i = tid; i < 792; i += 512) {
            int sy = i / 132, cx = i - sy * 132;
            int gy = y0 - 1 + sy, gx = cx - 1;
            bool ok = (unsigned)gz < 128u && (unsigned)gy < 128u &&
                      (unsigned)gx < 128u;
            const float* p = feat + (gz * 128 + gy) * 128 + gx;
            uint32_t hi[8], lo[8];     // 16 channels as 8 bf16x2 pairs
#pragma unroll
            for (int q = 0; q < 8; q++) {
                float a = ok ? __ldg(p + (2 * q) * DHWf) : 0.f;
                float b = ok ? __ldg(p + (2 * q + 1) * DHWf) : 0.f;
                __nv_bfloat16 ah = __float2bfloat16(a);
                __nv_bfloat16 bh = __float2bfloat16(b);
                hi[q] = packbf(ah, bh);
                lo[q] = packbf(__float2bfloat16(a - __bfloat162float(ah)),
                               __float2bfloat16(b - __bfloat162float(bh)));
            }
            char* rowp = dsm + sy * 4224;
            int o0 = (cx * 32)      ^ ((cx & 4) << 2);
            int o1 = (cx * 32 + 16) ^ ((cx & 4) << 2);
            *reinterpret_cast<uint4*>(rowp + o0) =
                make_uint4(hi[0], hi[1], hi[2], hi[3]);
            *reinterpret_cast<uint4*>(rowp + o1) =
                make_uint4(hi[4], hi[5], hi[6], hi[7]);
            *reinterpret_cast<uint4*>(rowp + PLANE + o0) =
                make_uint4(lo[0], lo[1], lo[2], lo[3]);
            *reinterpret_cast<uint4*>(rowp + PLANE + o1) =
                make_uint4(lo[4], lo[5], lo[6], lo[7]);
        }
        __syncthreads();

        // ---- MMA phase: this warp's kz (at most one per fz) ----------------
        int kz = fz - oz_w;
        if (kz >= 0 && kz <= 2) {
#pragma unroll
            for (int ky = 0; ky < 3; ky++) {
                uint32_t rbh = sb + (uint32_t)((oy_w + ky) * 4224);
                uint32_t rbl = rbh + PLANE;
#pragma unroll
                for (int kx = 0; kx < 3; kx++) {
                    int t = kz * 9 + ky * 3 + kx;
                    uint32_t bh0, bh1, bl0, bl1;
                    asm volatile("ld.shared.v2.u32 {%0, %1}, [%2];"
                                 : "=r"(bh0), "=r"(bh1)
                                 : "r"(sb + BHOFF + t * 256 + lane * 8));
                    asm volatile("ld.shared.v2.u32 {%0, %1}, [%2];"
                                 : "=r"(bl0), "=r"(bl1)
                                 : "r"(sb + BLOFF + t * 256 + lane * 8));
#pragma unroll
                    for (int g = 0; g < 8; g++) {
                        uint32_t adh = rbh + g * 512 + off[kx];
                        uint32_t adl = rbl + g * 512 + off[kx];
                        uint32_t a0, a1, a2, a3, c0r, c1r, c2r, c3r;
                        asm volatile("ldmatrix.sync.aligned.m8n8.x4.shared.b16 "
                                     "{%0,%1,%2,%3}, [%4];"
                                     : "=r"(a0), "=r"(a1), "=r"(a2), "=r"(a3)
                                     : "r"(adh));
                        asm volatile("ldmatrix.sync.aligned.m8n8.x4.shared.b16 "
                                     "{%0,%1,%2,%3}, [%4];"
                                     : "=r"(c0r), "=r"(c1r), "=r"(c2r), "=r"(c3r)
                                     : "r"(adl));
                        asm volatile("mma.sync.aligned.m16n8k16.row.col.f32.bf16.bf16.f32 "
                                     "{%0,%1,%2,%3}, {%4,%5,%6,%7}, {%8,%9}, {%0,%1,%2,%3};"
                                     : "+f"(acc[g][0]), "+f"(acc[g][1]),
                                       "+f"(acc[g][2]), "+f"(acc[g][3])
                                     : "r"(a0), "r"(a1), "r"(a2), "r"(a3),
                                       "r"(bh0), "r"(bh1));
                        asm volatile("mma.sync.aligned.m16n8k16.row.col.f32.bf16.bf16.f32 "
                                     "{%0,%1,%2,%3}, {%4,%5,%6,%7}, {%8,%9}, {%0,%1,%2,%3};"
                                     : "+f"(acc[g][0]), "+f"(acc[g][1]),
                                       "+f"(acc[g][2]), "+f"(acc[g][3])
                                     : "r"(a0), "r"(a1), "r"(a2), "r"(a3),
                                       "r"(bl0), "r"(bl1));
                        asm volatile("mma.sync.aligned.m16n8k16.row.col.f32.bf16.bf16.f32 "
                                     "{%0,%1,%2,%3}, {%4,%5,%6,%7}, {%8,%9}, {%0,%1,%2,%3};"
                                     : "+f"(acc[g][0]), "+f"(acc[g][1]),
                                       "+f"(acc[g][2]), "+f"(acc[g][3])
                                     : "r"(c0r), "r"(c1r), "r"(c2r), "r"(c3r),
                                       "r"(bh0), "r"(bh1));
                    }
                }
            }
        }
    }
    __syncthreads();                  // all MMAs done; slab dead

    // ---- D fragments -> staging [voxel][16 B] (cols 0-3; col3 == 0) --------
    if (n0 < 4) {
        const int vb = (oz_w * 4 + oy_w) * 128;
#pragma unroll
        for (int g = 0; g < 8; g++) {
            int v = vb + g * 16 + (lane >> 2);
            *reinterpret_cast<float2*>(dsm + v * 16 + n0 * 4) =
                make_float2(acc[g][0], acc[g][1]);
            *reinterpret_cast<float2*>(dsm + (v + 8) * 16 + n0 * 4) =
                make_float2(acc[g][2], acc[g][3]);
        }
    }
    __syncthreads();

    // ---- staging -> g_pos4 (coalesced) --------------------------------------
#pragma unroll
    for (int i = 0; i < 4; i++) {
        int v = tid * 4 + i;
        float4 val = *reinterpret_cast<float4*>(dsm + v * 16);
        int x = v & 127, yl = (v >> 7) & 3, zl = v >> 9;
        g_pos4[(z0 + zl) * 16384 + (y0 + yl) * 128 + x] = val;  // .w == 0
    }
}

// ---------------------------------------------------------------------------
// f0 = resize(pos_flow, 64^3) * (1/2) * (1/2^7)
// ---------------------------------------------------------------------------
__global__ void resize_down_kernel() {
    int idx = blockIdx.x * blockDim.x + threadIdx.x;
    if (idx >= DHWs) return;
    int k = idx & 63, j = (idx >> 6) & 63, i = idx >> 12;
    const float S = 127.f / 63.f;
    float3 o = sample_flow(g_pos4, DD, i * S, j * S, k * S);
    const float sc = 1.f / 256.f;
    g_fa[idx] = make_float4(o.x * sc, o.y * sc, o.z * sc, 0.f);
}

// ---------------------------------------------------------------------------
// scaling-and-squaring step: dst = f + warp(f, f)
// ---------------------------------------------------------------------------
__global__ void vecint_kernel(int it) {
    const float4* __restrict__ src = (it & 1) ? g_fb : g_fa;
    float4*       __restrict__ dst = (it & 1) ? g_fa : g_fb;
    int idx = blockIdx.x * blockDim.x + threadIdx.x;
    if (idx >= DHWs) return;
    int k = idx & 63, j = (idx >> 6) & 63, i = idx >> 12;
    float4 f = __ldg(src + idx);
    float3 o = sample_flow(src, DS, i + f.x, j + f.y, k + f.z);
    dst[idx] = make_float4(f.x + o.x, f.y + o.y, f.z + o.z, 0.f);
}

// ---------------------------------------------------------------------------
// flow = resize(f * 2, 128^3); moved = warp(label, flow)
// ---------------------------------------------------------------------------
__global__ void upsample_warp_kernel(const float* __restrict__ label,
                                     float* __restrict__ out) {
    int t = blockIdx.x * blockDim.x + threadIdx.x;
    if (t >= DHWf / 4) return;
    int x0 = (t & 31) * 4;
    int y  = (t >> 5) & 127;
    int z  = t >> 12;
    const float S = 63.f / 127.f;

    float pz = z * S, py = y * S;
    float fz = floorf(pz), fy = floorf(py);
    int z0 = (int)fz, y0 = (int)fy;
    float tz = pz - fz, ty = py - fy;
    int z1 = min(z0 + 1, DS - 1), y1 = min(y0 + 1, DS - 1);
    float wzy[4];
    wzy[0] = (1.f - tz) * (1.f - ty);
    wzy[1] = (1.f - tz) * ty;
    wzy[2] = tz * (1.f - ty);
    wzy[3] = tz * ty;
    const float4* rowp[4];
    rowp[0] = g_fb + (z0 * DS + y0) * DS;
    rowp[1] = g_fb + (z0 * DS + y1) * DS;
    rowp[2] = g_fb + (z1 * DS + y0) * DS;
    rowp[3] = g_fb + (z1 * DS + y1) * DS;

    float4 mv, oz, oy, ox;
    float* pm = &mv.x; float* pzo = &oz.x; float* pyo = &oy.x; float* pxo = &ox.x;
#pragma unroll
    for (int q = 0; q < 4; q++) {
        int x = x0 + q;
        float px = x * S;
        float fx = floorf(px);
        int xi0 = (int)fx;
        float txf = px - fx;
        int xi1 = min(xi0 + 1, DS - 1);

        float az = 0.f, ay = 0.f, ax = 0.f;
#pragma unroll
        for (int ab = 0; ab < 4; ab++) {
            float4 v0 = __ldg(rowp[ab] + xi0);
            float4 v1 = __ldg(rowp[ab] + xi1);
            float w0 = wzy[ab] * (1.f - txf);
            float w1 = wzy[ab] * txf;
            az += w0 * v0.x + w1 * v1.x;
            ay += w0 * v0.y + w1 * v1.y;
            ax += w0 * v0.z + w1 * v1.z;
        }
        float flz = 2.f * az, fly = 2.f * ay, flx = 2.f * ax;
        pzo[q] = flz;  pyo[q] = fly;  pxo[q] = flx;
        pm[q] = sample_scalar(label, DD, z + flz, y + fly, x + flx);
    }
    int base = (z * 128 + y) * 128 + x0;
    *reinterpret_cast<float4*>(out + base)            = mv;
    *reinterpret_cast<float4*>(out + DHWf + base)     = oz;
    *reinterpret_cast<float4*>(out + 2 * DHWf + base) = oy;
    *reinterpret_cast<float4*>(out + 3 * DHWf + base) = ox;
}

// ---------------------------------------------------------------------------
extern "C" void kernel_launch(void* const* d_in, const int* in_sizes, int n_in,
                              void* d_out, int out_size) {
    const float* feat  = (const float*)d_in[0];
    const float* label = (const float*)d_in[1];
    const float* wgt   = (const float*)d_in[2];
    const float* bias  = (const float*)d_in[3];
    float* out = (float*)d_out;

    cudaFuncSetAttribute(conv3d_tc_kernel,
                         cudaFuncAttributeMaxDynamicSharedMemorySize, CSMEM);
    conv3d_tc_kernel<<<dim3(32, 32), 512, CSMEM>>>(feat, wgt, bias);

    resize_down_kernel<<<DHWs / 256, 256>>>();
    for (int it = 0; it < 7; it++)
        vecint_kernel<<<DHWs / 256, 256>>>(it);
    upsample_warp_kernel<<<(DHWf / 4) / 256, 256>>>(label, out);
}